// round 1
// baseline (speedup 1.0000x reference)
#include <cuda_runtime.h>

// OT_Loss: batched Sinkhorn optimal transport.
// B=128 images, N=1024 points, 16x16 grid (256 cells), REG=10, <=100 iters.
// Key structure: dis[n, j*16+i] = (py_n - c_j)^2 + (px_n - c_i)^2
//   => K[n, j*16+i] = Ky[n][j] * Kx[n][i]  (separable; never materialize K)
// One block per image. Ky/Kx kept in SMEM (transposed, padded). Early exit when
// v stops changing (deterministic in-kernel check): Sinkhorn with REG=10 on this
// cost range contracts ~10x per iteration.

#define NPTS    1024
#define OUT16   16
#define P2      256
#define REGP    10.0f
#define TSTRIDE 1028   // 1024 + 4 pad (floats) -> conflict-free float4 columns

__device__ float g_partial[128 * 3];

__global__ void __launch_bounds__(256, 1) ot_kernel(
    const float* __restrict__ nd,   // [128, 256] normed density
    const float* __restrict__ ud,   // [128, 256] unnormed density
    const float* __restrict__ pts)  // [128, 1024, 2]
{
    extern __shared__ float sm[];
    float* KxT   = sm;                    // [16][TSTRIDE]
    float* KyT   = KxT  + 16 * TSTRIDE;   // [16][TSTRIDE]
    float* AuyT  = KyT  + 16 * TSTRIDE;   // [16][TSTRIDE]  (u[n]*Ky[n][j])
    float* us    = AuyT + 16 * TSTRIDE;   // [1024]
    float* pxs   = us   + 1024;           // [1024]
    float* pys   = pxs  + 1024;           // [1024]
    float* Vs    = pys  + 1024;           // [256]
    float* bsh   = Vs   + 256;            // [256]  (= nd, the source prob)
    float* beta_ = bsh  + 256;            // [256]  (unused scratch / beta)
    float* red   = beta_ + 256;           // [32]
    __shared__ int s_conv;

    const int tid = threadIdx.x;
    const int img = blockIdx.x;
    const float a_val = 1.0f / 1024.0f;

    // grid coordinates c_i = ((16i+8)/256)*2 - 1
    float cood[16];
#pragma unroll
    for (int i = 0; i < 16; i++)
        cood[i] = (float)(16 * i + 8) * (1.0f / 256.0f) * 2.0f - 1.0f;

    // source prob b = nd
    bsh[tid] = nd[img * 256 + tid];
    Vs[tid]  = 1.0f / 256.0f;   // v0 (for the first convergence delta only)
    if (tid == 0) s_conv = 0;

    // ---- setup: build Kx, Ky (transposed) + init u ----
#pragma unroll
    for (int k = 0; k < 4; k++) {
        int n = tid + k * 256;
        float x = pts[img * 2048 + 2 * n];
        float y = pts[img * 2048 + 2 * n + 1];
        float px = x * (2.0f / 256.0f) - 1.0f;
        float py = y * (2.0f / 256.0f) - 1.0f;
        pxs[n] = px; pys[n] = py;
        us[n] = a_val;
#pragma unroll
        for (int i = 0; i < 16; i++) {
            float dx = px - cood[i];
            float dy = py - cood[i];
            float kxv = expf(dx * dx * (-1.0f / REGP));
            float kyv = expf(dy * dy * (-1.0f / REGP));
            KxT[i * TSTRIDE + n]  = kxv;
            KyT[i * TSTRIDE + n]  = kyv;
            AuyT[i * TSTRIDE + n] = a_val * kyv;   // u0 * Ky
        }
    }
    __syncthreads();

    const int vj = tid >> 4;
    const int vi = tid & 15;
    const float4* Arow = (const float4*)(AuyT + vj * TSTRIDE);
    const float4* Xrow = (const float4*)(KxT  + vi * TSTRIDE);
    const float bval = bsh[tid];

    // ---- Sinkhorn iterations (max 100, early exit on convergence) ----
    for (int it = 0; it < 100; ++it) {
        // v-pass: v[j*16+i] = b / (sum_n (u*Ky)[n][j] * Kx[n][i] + eps)
        float a0 = 0.f, a1 = 0.f, a2 = 0.f, a3 = 0.f;
#pragma unroll 8
        for (int q = 0; q < 256; q++) {
            float4 av = Arow[q];
            float4 xv = Xrow[q];
            a0 = fmaf(av.x, xv.x, a0);
            a1 = fmaf(av.y, xv.y, a1);
            a2 = fmaf(av.z, xv.z, a2);
            a3 = fmaf(av.w, xv.w, a3);
        }
        float acc  = (a0 + a1) + (a2 + a3);
        float newv = bval / (acc + 1e-16f);
        float oldv = Vs[tid];
        Vs[tid] = newv;

        // convergence metric: max relative change of v over the block
        float rd = fabsf(newv - oldv) / (fabsf(newv) + 1e-30f);
#pragma unroll
        for (int o = 16; o > 0; o >>= 1)
            rd = fmaxf(rd, __shfl_xor_sync(0xffffffffu, rd, o));
        if ((tid & 31) == 0) red[tid >> 5] = rd;
        __syncthreads();   // Vs + red visible
        if (tid == 0) {
            float m = red[0];
#pragma unroll
            for (int w = 1; w < 8; w++) m = fmaxf(m, red[w]);
            if (m < 1e-6f) s_conv = 1;
        }

        // u-pass: u[n] = a / (sum_j Ky[n][j] * sum_i Kx[n][i]*V[j][i] + eps)
        const float4* Vf = (const float4*)Vs;
#pragma unroll
        for (int k = 0; k < 4; k++) {
            int n = tid + k * 256;
            float kx[16], ky[16];
#pragma unroll
            for (int i = 0; i < 16; i++) {
                kx[i] = KxT[i * TSTRIDE + n];
                ky[i] = KyT[i * TSTRIDE + n];
            }
            float s0 = 0.f, s1 = 0.f;
#pragma unroll
            for (int j = 0; j < 16; j++) {
                float4 v0 = Vf[4 * j + 0];
                float4 v1 = Vf[4 * j + 1];
                float4 v2 = Vf[4 * j + 2];
                float4 v3 = Vf[4 * j + 3];
                float w0 = fmaf(kx[0],  v0.x, fmaf(kx[1],  v0.y, fmaf(kx[2],  v0.z, kx[3]  * v0.w)));
                float w1 = fmaf(kx[4],  v1.x, fmaf(kx[5],  v1.y, fmaf(kx[6],  v1.z, kx[7]  * v1.w)));
                float w2 = fmaf(kx[8],  v2.x, fmaf(kx[9],  v2.y, fmaf(kx[10], v2.z, kx[11] * v2.w)));
                float w3 = fmaf(kx[12], v3.x, fmaf(kx[13], v3.y, fmaf(kx[14], v3.z, kx[15] * v3.w)));
                float w = (w0 + w1) + (w2 + w3);
                if (j & 1) s1 = fmaf(ky[j], w, s1);
                else       s0 = fmaf(ky[j], w, s0);
            }
            float s  = s0 + s1;
            float un = a_val / (s + 1e-16f);
            us[n] = un;
#pragma unroll
            for (int i = 0; i < 16; i++)
                AuyT[i * TSTRIDE + n] = un * ky[i];
        }
        __syncthreads();   // AuyT/us visible; s_conv (written before this barrier) visible
        if (s_conv) break;
    }

    // ---- epilogue ----
    float* scratch = AuyT;   // 16448 floats free now
    const float udv = ud[img * 256 + tid];
    const float ndv = bsh[tid];
    const float bt  = REGP * logf(Vs[tid] + 1e-16f);   // beta

    scratch[tid]       = ndv * bt;   // -> ot
    scratch[256 + tid] = udv;        // -> sc
    scratch[512 + tid] = udv * bt;   // -> S
    __syncthreads();
#pragma unroll
    for (int st = 128; st > 0; st >>= 1) {
        if (tid < st) {
            scratch[tid]       += scratch[tid + st];
            scratch[256 + tid] += scratch[256 + tid + st];
            scratch[512 + tid] += scratch[512 + tid + st];
        }
        __syncthreads();
    }
    const float ot = scratch[0];
    const float sc = scratch[256];
    const float S  = scratch[512];
    const float denom = sc * sc + 1e-8f;
    const float lv = udv * ((sc / denom) * bt - S / denom);

    // wd = sum_n u[n] * sum_j Ky[n][j] * ( ydis_j * t1_j + t2_j )
    //   t1_j = sum_i Kx[n][i]*V[j][i],  t2_j = sum_i xdis_i*Kx[n][i]*V[j][i]
    float wdp = 0.f;
#pragma unroll
    for (int k = 0; k < 4; k++) {
        int n = tid + k * 256;
        float px = pxs[n], py = pys[n], un = us[n];
        float kx[16], ky[16];
#pragma unroll
        for (int i = 0; i < 16; i++) {
            kx[i] = KxT[i * TSTRIDE + n];
            ky[i] = KyT[i * TSTRIDE + n];
        }
        float contrib = 0.f;
#pragma unroll
        for (int j = 0; j < 16; j++) {
            float dy = py - cood[j];
            float ydis = dy * dy;
            float t1 = 0.f, t2 = 0.f;
#pragma unroll
            for (int i = 0; i < 16; i++) {
                float kv = kx[i] * Vs[j * 16 + i];
                t1 += kv;
                float dx = px - cood[i];
                t2 = fmaf(dx * dx, kv, t2);
            }
            contrib = fmaf(ky[j], fmaf(ydis, t1, t2), contrib);
        }
        wdp = fmaf(un, contrib, wdp);
    }

    __syncthreads();   // everyone has read ot/sc/S before scratch reuse
    scratch[tid]       = lv;
    scratch[256 + tid] = wdp;
    __syncthreads();
#pragma unroll
    for (int st = 128; st > 0; st >>= 1) {
        if (tid < st) {
            scratch[tid]       += scratch[tid + st];
            scratch[256 + tid] += scratch[256 + tid + st];
        }
        __syncthreads();
    }
    if (tid == 0) {
        g_partial[img * 3 + 0] = scratch[0];     // loss
        g_partial[img * 3 + 1] = scratch[256];   // wd
        g_partial[img * 3 + 2] = ot;             // ot_obj
    }
}

// Deterministic fixed-tree reduction of per-image partials into the 3 outputs.
__global__ void ot_reduce_kernel(float* __restrict__ out)
{
    __shared__ float s[128];
    int t = threadIdx.x;
#pragma unroll
    for (int c = 0; c < 3; c++) {
        s[t] = g_partial[t * 3 + c];
        __syncthreads();
#pragma unroll
        for (int st = 64; st > 0; st >>= 1) {
            if (t < st) s[t] += s[t + st];
            __syncthreads();
        }
        if (t == 0) out[c] = s[0];
        __syncthreads();
    }
}

extern "C" void kernel_launch(void* const* d_in, const int* in_sizes, int n_in,
                              void* d_out, int out_size)
{
    const float* nd  = (const float*)d_in[0];
    const float* ud  = (const float*)d_in[1];
    const float* pts = (const float*)d_in[2];
    // (d_in[3] = scale = 16, compile-time constant here)

    size_t smem = (size_t)(3 * 16 * TSTRIDE + 3 * 1024 + 3 * 256 + 32) * sizeof(float);
    cudaFuncSetAttribute(ot_kernel, cudaFuncAttributeMaxDynamicSharedMemorySize, (int)smem);
    ot_kernel<<<128, 256, smem>>>(nd, ud, pts);
    ot_reduce_kernel<<<1, 128>>>((float*)d_out);
}

// round 2
// speedup vs baseline: 1.2097x; 1.2097x over previous
#include <cuda_runtime.h>

// OT_Loss: batched Sinkhorn OT. B=128 images, N=1024 points, 16x16 grid, REG=10.
// Separable kernel K[n][j*16+i] = Ky[n][j]*Kx[n][i]; never materialize K.
// R2: fma.rn.f32x2 packed math, 512 threads, conflict-free 2x2-tiled v-pass,
// looser (still safe) convergence threshold, fused final reduction.

#define REGP     10.0f
#define TSTRIDE  1028          // floats; 16B-aligned rows, bank shift 4 per row
#define CONV_TOL 3e-4f

typedef unsigned long long u64t;

__device__ __forceinline__ u64t pack2(float a, float b) {
    u64t r; asm("mov.b64 %0, {%1, %2};" : "=l"(r) : "f"(a), "f"(b)); return r;
}
__device__ __forceinline__ void fma2(u64t& d, u64t a, u64t b) {
    asm("fma.rn.f32x2 %0, %1, %2, %0;" : "+l"(d) : "l"(a), "l"(b));
}
__device__ __forceinline__ float hsum2(u64t a, u64t b) {
    float ax, ay, bx, by;
    asm("mov.b64 {%0, %1}, %2;" : "=f"(ax), "=f"(ay) : "l"(a));
    asm("mov.b64 {%0, %1}, %2;" : "=f"(bx), "=f"(by) : "l"(b));
    return (ax + ay) + (bx + by);
}

__device__ float        g_partial[128 * 3];
__device__ unsigned int g_ctr = 0;

__global__ void __launch_bounds__(512, 1) ot_kernel(
    const float* __restrict__ nd,   // [128,256]
    const float* __restrict__ ud,   // [128,256]
    const float* __restrict__ pts,  // [128,1024,2]
    float* __restrict__ out)        // [3]
{
    extern __shared__ float sm[];
    float* KxT  = sm;                    // [16][TSTRIDE]
    float* KyT  = KxT  + 16 * TSTRIDE;
    float* AuyT = KyT  + 16 * TSTRIDE;   // u[n]*Ky[n][j]
    float* us   = AuyT + 16 * TSTRIDE;   // [1024]
    float* pxs  = us   + 1024;
    float* pys  = pxs  + 1024;
    float* Vs   = pys  + 1024;           // [256]
    float* bsh  = Vs   + 256;            // [256]
    float* part = bsh  + 256;            // [2048]
    float* red  = part + 2048;           // [32]
    __shared__ int s_conv, s_last;

    const int tid = threadIdx.x;
    const int img = blockIdx.x;
    const float a_val = 1.0f / 1024.0f;

    float cood[16];
#pragma unroll
    for (int i = 0; i < 16; i++)
        cood[i] = (float)(16 * i + 8) * (1.0f / 256.0f) * 2.0f - 1.0f;

    if (tid < 256) { bsh[tid] = nd[img * 256 + tid]; Vs[tid] = 1.0f / 256.0f; }
    if (tid == 0) s_conv = 0;

    // ---- setup ----
#pragma unroll
    for (int k = 0; k < 2; k++) {
        int n = tid + (k << 9);
        float x = pts[img * 2048 + 2 * n];
        float y = pts[img * 2048 + 2 * n + 1];
        float px = x * (2.0f / 256.0f) - 1.0f;
        float py = y * (2.0f / 256.0f) - 1.0f;
        pxs[n] = px; pys[n] = py; us[n] = a_val;
#pragma unroll
        for (int i = 0; i < 16; i++) {
            float dx = px - cood[i];
            float dy = py - cood[i];
            float kxv = expf(dx * dx * (-1.0f / REGP));
            float kyv = expf(dy * dy * (-1.0f / REGP));
            KxT[i * TSTRIDE + n]  = kxv;
            KyT[i * TSTRIDE + n]  = kyv;
            AuyT[i * TSTRIDE + n] = a_val * kyv;
        }
    }
    __syncthreads();

    // v-pass tiling: thread = (h, j, i); computes M for {j,j+8}x{i,i+8} over n-octant h
    const int hh = tid >> 6;          // 0..7
    const int jj = (tid >> 3) & 7;    // 0..7
    const int ii = tid & 7;           // 0..7
    const ulonglong2* A0 = (const ulonglong2*)(AuyT + jj * TSTRIDE)       + hh * 32;
    const ulonglong2* A1 = (const ulonglong2*)(AuyT + (jj + 8) * TSTRIDE) + hh * 32;
    const ulonglong2* X0 = (const ulonglong2*)(KxT  + ii * TSTRIDE)       + hh * 32;
    const ulonglong2* X1 = (const ulonglong2*)(KxT  + (ii + 8) * TSTRIDE) + hh * 32;

    // ---- Sinkhorn loop ----
    for (int it = 0; it < 100; ++it) {
        // v-pass partials
        u64t c00a = 0, c00b = 0, c01a = 0, c01b = 0;
        u64t c10a = 0, c10b = 0, c11a = 0, c11b = 0;
#pragma unroll 8
        for (int q = 0; q < 32; q++) {
            ulonglong2 a0 = A0[q], a1 = A1[q], x0 = X0[q], x1 = X1[q];
            fma2(c00a, a0.x, x0.x); fma2(c00b, a0.y, x0.y);
            fma2(c01a, a0.x, x1.x); fma2(c01b, a0.y, x1.y);
            fma2(c10a, a1.x, x0.x); fma2(c10b, a1.y, x0.y);
            fma2(c11a, a1.x, x1.x); fma2(c11b, a1.y, x1.y);
        }
        part[hh * 256 + jj * 16 + ii]            = hsum2(c00a, c00b);
        part[hh * 256 + jj * 16 + ii + 8]        = hsum2(c01a, c01b);
        part[hh * 256 + (jj + 8) * 16 + ii]      = hsum2(c10a, c10b);
        part[hh * 256 + (jj + 8) * 16 + ii + 8]  = hsum2(c11a, c11b);
        __syncthreads();

        // combine + v update + convergence metric
        if (tid < 256) {
            float s = part[tid];
#pragma unroll
            for (int h = 1; h < 8; h++) s += part[h * 256 + tid];
            float newv = bsh[tid] / (s + 1e-16f);
            float oldv = Vs[tid];
            Vs[tid] = newv;
            float rd = fabsf(newv - oldv) / (fabsf(newv) + 1e-30f);
#pragma unroll
            for (int o = 16; o > 0; o >>= 1)
                rd = fmaxf(rd, __shfl_xor_sync(0xffffffffu, rd, o));
            if ((tid & 31) == 0) red[tid >> 5] = rd;
        }
        __syncthreads();   // Vs + red visible
        if (tid == 0) {
            float m = red[0];
#pragma unroll
            for (int w = 1; w < 8; w++) m = fmaxf(m, red[w]);
            if (m < CONV_TOL) s_conv = 1;
        }

        // u-pass: per n, s = sum_i kx[i] * (sum_j ky[j]*V[j][i])
#pragma unroll
        for (int k = 0; k < 2; k++) {
            int n = tid + (k << 9);
            float ky[16];
#pragma unroll
            for (int i = 0; i < 16; i++) ky[i] = KyT[i * TSTRIDE + n];
            u64t zp[8] = {0, 0, 0, 0, 0, 0, 0, 0};
#pragma unroll
            for (int j = 0; j < 16; j++) {
                u64t kj = pack2(ky[j], ky[j]);
                const ulonglong2* Vr = (const ulonglong2*)(Vs + j * 16);
                ulonglong2 v0 = Vr[0], v1 = Vr[1], v2 = Vr[2], v3 = Vr[3];
                fma2(zp[0], kj, v0.x); fma2(zp[1], kj, v0.y);
                fma2(zp[2], kj, v1.x); fma2(zp[3], kj, v1.y);
                fma2(zp[4], kj, v2.x); fma2(zp[5], kj, v2.y);
                fma2(zp[6], kj, v3.x); fma2(zp[7], kj, v3.y);
            }
            float kx[16];
#pragma unroll
            for (int i = 0; i < 16; i++) kx[i] = KxT[i * TSTRIDE + n];
            u64t sa = 0, sb = 0;
            fma2(sa, pack2(kx[0],  kx[1]),  zp[0]);
            fma2(sb, pack2(kx[2],  kx[3]),  zp[1]);
            fma2(sa, pack2(kx[4],  kx[5]),  zp[2]);
            fma2(sb, pack2(kx[6],  kx[7]),  zp[3]);
            fma2(sa, pack2(kx[8],  kx[9]),  zp[4]);
            fma2(sb, pack2(kx[10], kx[11]), zp[5]);
            fma2(sa, pack2(kx[12], kx[13]), zp[6]);
            fma2(sb, pack2(kx[14], kx[15]), zp[7]);
            float s = hsum2(sa, sb);
            float un = a_val / (s + 1e-16f);
            us[n] = un;
#pragma unroll
            for (int i = 0; i < 16; i++)
                AuyT[i * TSTRIDE + n] = un * ky[i];
        }
        __syncthreads();
        if (s_conv) break;
    }

    // ---- epilogue: ot, sc, S over the 256 cells ----
    float bt = 0.f, udv = 0.f;
    if (tid < 256) {
        udv = ud[img * 256 + tid];
        bt  = REGP * logf(Vs[tid] + 1e-16f);        // beta
        part[tid]       = bsh[tid] * bt;            // -> ot
        part[256 + tid] = udv;                      // -> sc
        part[512 + tid] = udv * bt;                 // -> S
    }
    __syncthreads();
#pragma unroll
    for (int st = 128; st > 0; st >>= 1) {
        if (tid < st) {
            part[tid]       += part[tid + st];
            part[256 + tid] += part[256 + tid + st];
            part[512 + tid] += part[512 + tid + st];
        }
        __syncthreads();
    }
    const float ot = part[0];
    const float sc = part[256];
    const float S  = part[512];
    const float denom = sc * sc + 1e-8f;
    const float lv = (tid < 256) ? udv * ((sc / denom) * bt - S / denom) : 0.f;

    // wd = sum_n u_n * [ sum_i kx_i*xdis_i*z_i + sum_i kx_i*zy_i ]
    //   z_i  = sum_j ky_j V[j][i],  zy_i = sum_j ky_j*ydis_j V[j][i]
    float wdp = 0.f;
#pragma unroll
    for (int k = 0; k < 2; k++) {
        int n = tid + (k << 9);
        float px = pxs[n], py = pys[n], un = us[n];
        float ky[16];
#pragma unroll
        for (int i = 0; i < 16; i++) ky[i] = KyT[i * TSTRIDE + n];
        u64t zp[8]  = {0, 0, 0, 0, 0, 0, 0, 0};
        u64t zyp[8] = {0, 0, 0, 0, 0, 0, 0, 0};
#pragma unroll
        for (int j = 0; j < 16; j++) {
            float dy = py - cood[j];
            float kyy = ky[j] * dy * dy;
            u64t kj  = pack2(ky[j], ky[j]);
            u64t kjy = pack2(kyy, kyy);
            const ulonglong2* Vr = (const ulonglong2*)(Vs + j * 16);
            ulonglong2 v0 = Vr[0], v1 = Vr[1], v2 = Vr[2], v3 = Vr[3];
            fma2(zp[0], kj, v0.x);  fma2(zp[1], kj, v0.y);
            fma2(zp[2], kj, v1.x);  fma2(zp[3], kj, v1.y);
            fma2(zp[4], kj, v2.x);  fma2(zp[5], kj, v2.y);
            fma2(zp[6], kj, v3.x);  fma2(zp[7], kj, v3.y);
            fma2(zyp[0], kjy, v0.x); fma2(zyp[1], kjy, v0.y);
            fma2(zyp[2], kjy, v1.x); fma2(zyp[3], kjy, v1.y);
            fma2(zyp[4], kjy, v2.x); fma2(zyp[5], kjy, v2.y);
            fma2(zyp[6], kjy, v3.x); fma2(zyp[7], kjy, v3.y);
        }
        float kx[16];
#pragma unroll
        for (int i = 0; i < 16; i++) kx[i] = KxT[i * TSTRIDE + n];
        u64t sa = 0, sb = 0;
#pragma unroll
        for (int p = 0; p < 8; p++) {
            float dx0 = px - cood[2 * p];
            float dx1 = px - cood[2 * p + 1];
            u64t kxx = pack2(kx[2 * p] * dx0 * dx0, kx[2 * p + 1] * dx1 * dx1);
            u64t kxp = pack2(kx[2 * p], kx[2 * p + 1]);
            fma2(sa, kxx, zp[p]);
            fma2(sb, kxp, zyp[p]);
        }
        wdp = fmaf(un, hsum2(sa, sb), wdp);
    }

    __syncthreads();   // ot/sc/S consumed; safe to reuse part
    part[tid]       = lv;
    part[512 + tid] = wdp;
    __syncthreads();
#pragma unroll
    for (int st = 256; st > 0; st >>= 1) {
        if (tid < st) {
            part[tid]       += part[tid + st];
            part[512 + tid] += part[512 + tid + st];
        }
        __syncthreads();
    }

    if (tid == 0) {
        g_partial[img * 3 + 0] = part[0];
        g_partial[img * 3 + 1] = part[512];
        g_partial[img * 3 + 2] = ot;
        __threadfence();
        unsigned int old = atomicAdd(&g_ctr, 1u);
        s_last = (old == 127u) ? 1 : 0;
    }
    __syncthreads();

    // last-arriving block reduces the 128 per-image partials (fixed tree)
    if (s_last) {
        if (tid == 0) atomicExch(&g_ctr, 0u);
        __threadfence();
        if (tid < 128) {
            part[tid]       = __ldcg(&g_partial[tid * 3 + 0]);
            part[256 + tid] = __ldcg(&g_partial[tid * 3 + 1]);
            part[512 + tid] = __ldcg(&g_partial[tid * 3 + 2]);
        }
        __syncthreads();
#pragma unroll
        for (int st = 64; st > 0; st >>= 1) {
            if (tid < st) {
                part[tid]       += part[tid + st];
                part[256 + tid] += part[256 + tid + st];
                part[512 + tid] += part[512 + tid + st];
            }
            __syncthreads();
        }
        if (tid == 0) {
            out[0] = part[0];
            out[1] = part[256];
            out[2] = part[512];
        }
    }
}

extern "C" void kernel_launch(void* const* d_in, const int* in_sizes, int n_in,
                              void* d_out, int out_size)
{
    const float* nd  = (const float*)d_in[0];
    const float* ud  = (const float*)d_in[1];
    const float* pts = (const float*)d_in[2];

    size_t smem = (size_t)(3 * 16 * TSTRIDE + 3 * 1024 + 2 * 256 + 2048 + 32) * sizeof(float);
    cudaFuncSetAttribute(ot_kernel, cudaFuncAttributeMaxDynamicSharedMemorySize, (int)smem);
    ot_kernel<<<128, 512, smem>>>(nd, ud, pts, (float*)d_out);
}

// round 3
// speedup vs baseline: 2.2212x; 1.8361x over previous
#include <cuda_runtime.h>

// OT_Loss: batched Sinkhorn OT. B=128 images, N=1024 points, 16x16 grid, REG=10.
// Separable: K[n][j*16+i] = Ky[n][j]*Kx[n][i]. One block per image.
// R3: 1024 threads (32 warps), 1 point per thread; un/px/py in registers;
// v-pass tiled over 16 n-octants; fma.rn.f32x2 packed math throughout.

#define REGP     10.0f
#define TSTRIDE  1028          // floats; rows 16B-aligned (1028*4 = 257*16)
#define CONV_TOL 3e-4f

typedef unsigned long long u64t;

__device__ __forceinline__ u64t pack2(float a, float b) {
    u64t r; asm("mov.b64 %0, {%1, %2};" : "=l"(r) : "f"(a), "f"(b)); return r;
}
__device__ __forceinline__ void fma2(u64t& d, u64t a, u64t b) {
    asm("fma.rn.f32x2 %0, %1, %2, %0;" : "+l"(d) : "l"(a), "l"(b));
}
__device__ __forceinline__ float hsum2(u64t a, u64t b) {
    float ax, ay, bx, by;
    asm("mov.b64 {%0, %1}, %2;" : "=f"(ax), "=f"(ay) : "l"(a));
    asm("mov.b64 {%0, %1}, %2;" : "=f"(bx), "=f"(by) : "l"(b));
    return (ax + ay) + (bx + by);
}

__device__ float        g_partial[128 * 3];
__device__ unsigned int g_ctr = 0;

__global__ void __launch_bounds__(1024, 1) ot_kernel(
    const float* __restrict__ nd,   // [128,256]
    const float* __restrict__ ud,   // [128,256]
    const float* __restrict__ pts,  // [128,1024,2]
    float* __restrict__ out)        // [3]
{
    extern __shared__ float sm[];
    float* KxT  = sm;                    // [16][TSTRIDE]
    float* KyT  = KxT  + 16 * TSTRIDE;
    float* AuyT = KyT  + 16 * TSTRIDE;   // u[n]*Ky[n][j]
    float* Vs   = AuyT + 16 * TSTRIDE;   // [256]
    float* bsh  = Vs   + 256;            // [256]
    float* part = bsh  + 256;            // [4096]
    float* red  = part + 4096;           // [32]
    __shared__ int s_conv, s_last;

    const int tid = threadIdx.x;
    const int img = blockIdx.x;
    const float a_val = 1.0f / 1024.0f;

    float cood[16];
#pragma unroll
    for (int i = 0; i < 16; i++)
        cood[i] = (float)(16 * i + 8) * (1.0f / 256.0f) * 2.0f - 1.0f;

    if (tid < 256) { bsh[tid] = nd[img * 256 + tid]; Vs[tid] = 1.0f / 256.0f; }
    if (tid == 0) s_conv = 0;

    // ---- setup: one point per thread ----
    const float px = pts[img * 2048 + 2 * tid]     * (2.0f / 256.0f) - 1.0f;
    const float py = pts[img * 2048 + 2 * tid + 1] * (2.0f / 256.0f) - 1.0f;
    float un = a_val;
#pragma unroll
    for (int i = 0; i < 16; i++) {
        float dx = px - cood[i];
        float dy = py - cood[i];
        float kxv = expf(dx * dx * (-1.0f / REGP));
        float kyv = expf(dy * dy * (-1.0f / REGP));
        KxT[i * TSTRIDE + tid]  = kxv;
        KyT[i * TSTRIDE + tid]  = kyv;
        AuyT[i * TSTRIDE + tid] = a_val * kyv;
    }
    __syncthreads();

    // v-pass tiling: thread = (hh, jj, ii): 2x2 tile {jj,jj+8}x{ii,ii+8},
    // n-octant hh covers floats [hh*64, hh*64+64).
    const int hh = tid >> 6;          // 0..15
    const int jj = (tid >> 3) & 7;    // 0..7
    const int ii = tid & 7;           // 0..7
    const ulonglong2* A0 = (const ulonglong2*)(AuyT + jj * TSTRIDE)       + hh * 16;
    const ulonglong2* A1 = (const ulonglong2*)(AuyT + (jj + 8) * TSTRIDE) + hh * 16;
    const ulonglong2* X0 = (const ulonglong2*)(KxT  + ii * TSTRIDE)       + hh * 16;
    const ulonglong2* X1 = (const ulonglong2*)(KxT  + (ii + 8) * TSTRIDE) + hh * 16;

    // ---- Sinkhorn loop ----
    for (int it = 0; it < 100; ++it) {
        // v-pass partials over this thread's n-octant
        u64t c00a = 0, c00b = 0, c01a = 0, c01b = 0;
        u64t c10a = 0, c10b = 0, c11a = 0, c11b = 0;
#pragma unroll
        for (int q = 0; q < 16; q++) {
            ulonglong2 a0 = A0[q], a1 = A1[q], x0 = X0[q], x1 = X1[q];
            fma2(c00a, a0.x, x0.x); fma2(c00b, a0.y, x0.y);
            fma2(c01a, a0.x, x1.x); fma2(c01b, a0.y, x1.y);
            fma2(c10a, a1.x, x0.x); fma2(c10b, a1.y, x0.y);
            fma2(c11a, a1.x, x1.x); fma2(c11b, a1.y, x1.y);
        }
        part[hh * 256 + jj * 16 + ii]            = hsum2(c00a, c00b);
        part[hh * 256 + jj * 16 + ii + 8]        = hsum2(c01a, c01b);
        part[hh * 256 + (jj + 8) * 16 + ii]      = hsum2(c10a, c10b);
        part[hh * 256 + (jj + 8) * 16 + ii + 8]  = hsum2(c11a, c11b);
        __syncthreads();

        // combine + v update + convergence metric
        if (tid < 256) {
            float s = part[tid];
#pragma unroll
            for (int h = 1; h < 16; h++) s += part[h * 256 + tid];
            float newv = bsh[tid] / (s + 1e-16f);
            float oldv = Vs[tid];
            Vs[tid] = newv;
            float rd = fabsf(newv - oldv) / (fabsf(newv) + 1e-30f);
#pragma unroll
            for (int o = 16; o > 0; o >>= 1)
                rd = fmaxf(rd, __shfl_xor_sync(0xffffffffu, rd, o));
            if ((tid & 31) == 0) red[tid >> 5] = rd;
        }
        __syncthreads();   // Vs + red visible
        if (tid == 0) {
            float m = red[0];
#pragma unroll
            for (int w = 1; w < 8; w++) m = fmaxf(m, red[w]);
            if (m < CONV_TOL) s_conv = 1;
        }

        // u-pass: one point per thread.
        // z[i] = sum_j ky[j]*V[j][i]; s = sum_i kx[i]*z[i]
        {
            float ky[16];
#pragma unroll
            for (int i = 0; i < 16; i++) ky[i] = KyT[i * TSTRIDE + tid];
            u64t zp[8] = {0, 0, 0, 0, 0, 0, 0, 0};
#pragma unroll
            for (int j = 0; j < 16; j++) {
                u64t kj = pack2(ky[j], ky[j]);
                const ulonglong2* Vr = (const ulonglong2*)(Vs + j * 16);
                ulonglong2 v0 = Vr[0], v1 = Vr[1], v2 = Vr[2], v3 = Vr[3];
                fma2(zp[0], kj, v0.x); fma2(zp[1], kj, v0.y);
                fma2(zp[2], kj, v1.x); fma2(zp[3], kj, v1.y);
                fma2(zp[4], kj, v2.x); fma2(zp[5], kj, v2.y);
                fma2(zp[6], kj, v3.x); fma2(zp[7], kj, v3.y);
            }
            u64t sa = 0, sb = 0;
#pragma unroll
            for (int p = 0; p < 4; p++) {
                float kxa = KxT[(4 * p + 0) * TSTRIDE + tid];
                float kxb = KxT[(4 * p + 1) * TSTRIDE + tid];
                float kxc = KxT[(4 * p + 2) * TSTRIDE + tid];
                float kxd = KxT[(4 * p + 3) * TSTRIDE + tid];
                fma2(sa, pack2(kxa, kxb), zp[2 * p]);
                fma2(sb, pack2(kxc, kxd), zp[2 * p + 1]);
            }
            float s = hsum2(sa, sb);
            un = a_val / (s + 1e-16f);
#pragma unroll
            for (int i = 0; i < 16; i++)
                AuyT[i * TSTRIDE + tid] = un * ky[i];
        }
        __syncthreads();   // AuyT visible; s_conv (written pre-barrier) visible
        if (s_conv) break;
    }

    // ---- epilogue: ot, sc, S over the 256 cells ----
    float bt = 0.f, udv = 0.f;
    if (tid < 256) {
        udv = ud[img * 256 + tid];
        bt  = REGP * logf(Vs[tid] + 1e-16f);        // beta
        part[tid]       = bsh[tid] * bt;            // -> ot
        part[256 + tid] = udv;                      // -> sc
        part[512 + tid] = udv * bt;                 // -> S
    }
    __syncthreads();
#pragma unroll
    for (int st = 128; st > 0; st >>= 1) {
        if (tid < st) {
            part[tid]       += part[tid + st];
            part[256 + tid] += part[256 + tid + st];
            part[512 + tid] += part[512 + tid + st];
        }
        __syncthreads();
    }
    const float ot = part[0];
    const float sc = part[256];
    const float S  = part[512];
    const float denom = sc * sc + 1e-8f;
    const float lv = (tid < 256) ? udv * ((sc / denom) * bt - S / denom) : 0.f;

    // wd contribution of this thread's point:
    //   wd_n = u_n * [ sum_i kx_i*xdis_i*z_i + sum_i kx_i*zy_i ]
    //   z_i = sum_j ky_j V[j][i],  zy_i = sum_j ky_j*ydis_j V[j][i]
    float wdp;
    {
        float ky[16];
#pragma unroll
        for (int i = 0; i < 16; i++) ky[i] = KyT[i * TSTRIDE + tid];
        u64t zp[8]  = {0, 0, 0, 0, 0, 0, 0, 0};
        u64t zyp[8] = {0, 0, 0, 0, 0, 0, 0, 0};
#pragma unroll
        for (int j = 0; j < 16; j++) {
            float dy = py - cood[j];
            float kyy = ky[j] * dy * dy;
            u64t kj  = pack2(ky[j], ky[j]);
            u64t kjy = pack2(kyy, kyy);
            const ulonglong2* Vr = (const ulonglong2*)(Vs + j * 16);
            ulonglong2 v0 = Vr[0], v1 = Vr[1], v2 = Vr[2], v3 = Vr[3];
            fma2(zp[0], kj, v0.x);  fma2(zp[1], kj, v0.y);
            fma2(zp[2], kj, v1.x);  fma2(zp[3], kj, v1.y);
            fma2(zp[4], kj, v2.x);  fma2(zp[5], kj, v2.y);
            fma2(zp[6], kj, v3.x);  fma2(zp[7], kj, v3.y);
            fma2(zyp[0], kjy, v0.x); fma2(zyp[1], kjy, v0.y);
            fma2(zyp[2], kjy, v1.x); fma2(zyp[3], kjy, v1.y);
            fma2(zyp[4], kjy, v2.x); fma2(zyp[5], kjy, v2.y);
            fma2(zyp[6], kjy, v3.x); fma2(zyp[7], kjy, v3.y);
        }
        u64t sa = 0, sb = 0;
#pragma unroll
        for (int p = 0; p < 8; p++) {
            float kx0 = KxT[(2 * p) * TSTRIDE + tid];
            float kx1 = KxT[(2 * p + 1) * TSTRIDE + tid];
            float dx0 = px - cood[2 * p];
            float dx1 = px - cood[2 * p + 1];
            fma2(sa, pack2(kx0 * dx0 * dx0, kx1 * dx1 * dx1), zp[p]);
            fma2(sb, pack2(kx0, kx1), zyp[p]);
        }
        wdp = un * hsum2(sa, sb);
    }

    __syncthreads();   // ot/sc/S consumed; safe to reuse part
    part[tid]        = lv;    // tid>=256 wrote 0
    part[1024 + tid] = wdp;
    __syncthreads();
#pragma unroll
    for (int st = 512; st > 0; st >>= 1) {
        if (tid < st) {
            part[tid]        += part[tid + st];
            part[1024 + tid] += part[1024 + tid + st];
        }
        __syncthreads();
    }

    if (tid == 0) {
        g_partial[img * 3 + 0] = part[0];
        g_partial[img * 3 + 1] = part[1024];
        g_partial[img * 3 + 2] = ot;
        __threadfence();
        unsigned int old = atomicAdd(&g_ctr, 1u);
        s_last = (old == 127u) ? 1 : 0;
    }
    __syncthreads();

    // last-arriving block reduces the 128 per-image partials (fixed tree)
    if (s_last) {
        if (tid == 0) atomicExch(&g_ctr, 0u);
        __threadfence();
        if (tid < 128) {
            part[tid]       = __ldcg(&g_partial[tid * 3 + 0]);
            part[256 + tid] = __ldcg(&g_partial[tid * 3 + 1]);
            part[512 + tid] = __ldcg(&g_partial[tid * 3 + 2]);
        }
        __syncthreads();
#pragma unroll
        for (int st = 64; st > 0; st >>= 1) {
            if (tid < st) {
                part[tid]       += part[tid + st];
                part[256 + tid] += part[256 + tid + st];
                part[512 + tid] += part[512 + tid + st];
            }
            __syncthreads();
        }
        if (tid == 0) {
            out[0] = part[0];
            out[1] = part[256];
            out[2] = part[512];
        }
    }
}

extern "C" void kernel_launch(void* const* d_in, const int* in_sizes, int n_in,
                              void* d_out, int out_size)
{
    const float* nd  = (const float*)d_in[0];
    const float* ud  = (const float*)d_in[1];
    const float* pts = (const float*)d_in[2];

    size_t smem = (size_t)(3 * 16 * TSTRIDE + 2 * 256 + 4096 + 32) * sizeof(float);
    cudaFuncSetAttribute(ot_kernel, cudaFuncAttributeMaxDynamicSharedMemorySize, (int)smem);
    ot_kernel<<<128, 1024, smem>>>(nd, ud, pts, (float*)d_out);
}

// round 4
// speedup vs baseline: 2.3539x; 1.0597x over previous
#include <cuda_runtime.h>

// OT_Loss: batched Sinkhorn OT. B=128 images, N=1024 points, 16x16 grid, REG=10.
// Separable: K[n][j*16+i] = Ky[n][j]*Kx[n][i]. One block per image, 1024 threads.
// R4: recurrence-based exp setup, Aitken extrapolation at iter 3, float4
// partial stores, zp register reuse in the wd epilogue.

#define REGP     10.0f
#define TSTRIDE  1028          // floats; rows 16B-aligned (1028*4 = 257*16)
#define CONV_TOL 3e-4f
#define RHO      0.99687988f   // exp(-2*D^2/REG), D = 0.125

typedef unsigned long long u64t;

__device__ __forceinline__ u64t pack2(float a, float b) {
    u64t r; asm("mov.b64 %0, {%1, %2};" : "=l"(r) : "f"(a), "f"(b)); return r;
}
__device__ __forceinline__ void fma2(u64t& d, u64t a, u64t b) {
    asm("fma.rn.f32x2 %0, %1, %2, %0;" : "+l"(d) : "l"(a), "l"(b));
}
__device__ __forceinline__ float hsum2(u64t a, u64t b) {
    float ax, ay, bx, by;
    asm("mov.b64 {%0, %1}, %2;" : "=f"(ax), "=f"(ay) : "l"(a));
    asm("mov.b64 {%0, %1}, %2;" : "=f"(bx), "=f"(by) : "l"(b));
    return (ax + ay) + (bx + by);
}

__device__ float        g_partial[128 * 3];
__device__ unsigned int g_ctr = 0;

__global__ void __launch_bounds__(1024, 1) ot_kernel(
    const float* __restrict__ nd,   // [128,256]
    const float* __restrict__ ud,   // [128,256]
    const float* __restrict__ pts,  // [128,1024,2]
    float* __restrict__ out)        // [3]
{
    extern __shared__ float sm[];
    float* KxT  = sm;                    // [16][TSTRIDE]
    float* KyT  = KxT  + 16 * TSTRIDE;
    float* AuyT = KyT  + 16 * TSTRIDE;   // u[n]*Ky[n][j]
    float* Vs   = AuyT + 16 * TSTRIDE;   // [256]
    float* Vm1  = Vs   + 256;            // [256] v from two iterations ago
    float* bsh  = Vm1  + 256;            // [256]
    float* part = bsh  + 256;            // [4096]
    float* red  = part + 4096;           // [32]
    __shared__ int s_conv, s_last;

    const int tid = threadIdx.x;
    const int img = blockIdx.x;
    const float a_val = 1.0f / 1024.0f;

    float cood[16];
#pragma unroll
    for (int i = 0; i < 16; i++)
        cood[i] = (float)(16 * i + 8) * (1.0f / 256.0f) * 2.0f - 1.0f;

    if (tid < 256) { bsh[tid] = nd[img * 256 + tid]; Vs[tid] = 1.0f / 256.0f; }
    if (tid == 0) s_conv = 0;

    // ---- setup: one point per thread; kx/ky by geometric recurrence ----
    const float px = pts[img * 2048 + 2 * tid]     * (2.0f / 256.0f) - 1.0f;
    const float py = pts[img * 2048 + 2 * tid + 1] * (2.0f / 256.0f) - 1.0f;
    float un = a_val;
    {
        // kx[i+1] = kx[i]*r,  r *= RHO,  r0 = exp((2D(px-c0) - D^2)/REG)
        float dx0 = px - cood[0];
        float dy0 = py - cood[0];
        float kx = expf(dx0 * dx0 * (-1.0f / REGP));
        float ky = expf(dy0 * dy0 * (-1.0f / REGP));
        float rx = expf((0.25f * dx0 - 0.015625f) * (1.0f / REGP));
        float ry = expf((0.25f * dy0 - 0.015625f) * (1.0f / REGP));
#pragma unroll
        for (int i = 0; i < 16; i++) {
            KxT[i * TSTRIDE + tid]  = kx;
            KyT[i * TSTRIDE + tid]  = ky;
            AuyT[i * TSTRIDE + tid] = a_val * ky;
            kx *= rx; rx *= RHO;
            ky *= ry; ry *= RHO;
        }
    }
    __syncthreads();

    // v-pass tiling: thread = (hh, jj, ii): 2x2 tile {jj,jj+8}x{ii,ii+8},
    // n-chunk hh covers floats [hh*64, hh*64+64).
    const int hh = tid >> 6;          // 0..15
    const int jj = (tid >> 3) & 7;    // 0..7
    const int ii = tid & 7;           // 0..7
    const ulonglong2* A0 = (const ulonglong2*)(AuyT + jj * TSTRIDE)       + hh * 16;
    const ulonglong2* A1 = (const ulonglong2*)(AuyT + (jj + 8) * TSTRIDE) + hh * 16;
    const ulonglong2* X0 = (const ulonglong2*)(KxT  + ii * TSTRIDE)       + hh * 16;
    const ulonglong2* X1 = (const ulonglong2*)(KxT  + (ii + 8) * TSTRIDE) + hh * 16;
    float4* p4 = (float4*)part;
    // combine-read base for this thread's cell (tid<256): cell (j,i)=(tid>>4,tid&15)
    const int cj = tid >> 4, ci = tid & 15;
    const int cbase = (cj & 7) * 32 + (ci & 7) * 4 + (((cj >> 3) << 1) | (ci >> 3));

    u64t zp[8];   // persists: last u-pass's z_i pairs, reused in wd epilogue

    // ---- Sinkhorn loop ----
    for (int it = 0; it < 100; ++it) {
        // v-pass partials over this thread's n-chunk
        u64t c00a = 0, c00b = 0, c01a = 0, c01b = 0;
        u64t c10a = 0, c10b = 0, c11a = 0, c11b = 0;
#pragma unroll
        for (int q = 0; q < 16; q++) {
            ulonglong2 a0 = A0[q], a1 = A1[q], x0 = X0[q], x1 = X1[q];
            fma2(c00a, a0.x, x0.x); fma2(c00b, a0.y, x0.y);
            fma2(c01a, a0.x, x1.x); fma2(c01b, a0.y, x1.y);
            fma2(c10a, a1.x, x0.x); fma2(c10b, a1.y, x0.y);
            fma2(c11a, a1.x, x1.x); fma2(c11b, a1.y, x1.y);
        }
        p4[hh * 64 + jj * 8 + ii] = make_float4(
            hsum2(c00a, c00b), hsum2(c01a, c01b),
            hsum2(c10a, c10b), hsum2(c11a, c11b));
        __syncthreads();

        // combine + v update (+ Aitken at it==2) + convergence metric
        if (tid < 256) {
            const float* pb = part + cbase;
            float s0 = pb[0]        + pb[256];
            float s1 = pb[512]      + pb[768];
            float s2 = pb[1024]     + pb[1280];
            float s3 = pb[1536]     + pb[1792];
            float s4 = pb[2048]     + pb[2304];
            float s5 = pb[2560]     + pb[2816];
            float s6 = pb[3072]     + pb[3328];
            float s7 = pb[3584]     + pb[3840];
            float s = ((s0 + s1) + (s2 + s3)) + ((s4 + s5) + (s6 + s7));
            float newv = bsh[tid] / (s + 1e-16f);
            float oldv = Vs[tid];
            if (it == 2) {
                // Aitken delta^2: v* = v3 + d2*lam/(1-lam), lam = d2/d1
                float v1 = Vm1[tid];
                float d2 = newv - oldv;
                float d1 = oldv - v1;
                float lam = d2 / d1;
                if (fabsf(d1) > 1e-30f && lam > 0.0f && lam < 0.95f)
                    newv = newv + d2 * lam / (1.0f - lam);
            }
            Vm1[tid] = oldv;
            Vs[tid]  = newv;
            float rd = fabsf(newv - oldv) / (fabsf(newv) + 1e-30f);
#pragma unroll
            for (int o = 16; o > 0; o >>= 1)
                rd = fmaxf(rd, __shfl_xor_sync(0xffffffffu, rd, o));
            if ((tid & 31) == 0) red[tid >> 5] = rd;
        }
        __syncthreads();   // Vs + red visible
        if (tid == 0) {
            float m = red[0];
#pragma unroll
            for (int w = 1; w < 8; w++) m = fmaxf(m, red[w]);
            if (m < CONV_TOL) s_conv = 1;
        }

        // u-pass: z[i] = sum_j ky[j]*V[j][i]; s = sum_i kx[i]*z[i]
        {
            float ky[16];
#pragma unroll
            for (int i = 0; i < 16; i++) ky[i] = KyT[i * TSTRIDE + tid];
#pragma unroll
            for (int p = 0; p < 8; p++) zp[p] = 0;
#pragma unroll
            for (int j = 0; j < 16; j++) {
                u64t kj = pack2(ky[j], ky[j]);
                const ulonglong2* Vr = (const ulonglong2*)(Vs + j * 16);
                ulonglong2 v0 = Vr[0], v1 = Vr[1], v2 = Vr[2], v3 = Vr[3];
                fma2(zp[0], kj, v0.x); fma2(zp[1], kj, v0.y);
                fma2(zp[2], kj, v1.x); fma2(zp[3], kj, v1.y);
                fma2(zp[4], kj, v2.x); fma2(zp[5], kj, v2.y);
                fma2(zp[6], kj, v3.x); fma2(zp[7], kj, v3.y);
            }
            u64t sa = 0, sb = 0;
#pragma unroll
            for (int p = 0; p < 4; p++) {
                float kxa = KxT[(4 * p + 0) * TSTRIDE + tid];
                float kxb = KxT[(4 * p + 1) * TSTRIDE + tid];
                float kxc = KxT[(4 * p + 2) * TSTRIDE + tid];
                float kxd = KxT[(4 * p + 3) * TSTRIDE + tid];
                fma2(sa, pack2(kxa, kxb), zp[2 * p]);
                fma2(sb, pack2(kxc, kxd), zp[2 * p + 1]);
            }
            float s = hsum2(sa, sb);
            un = a_val / (s + 1e-16f);
#pragma unroll
            for (int i = 0; i < 16; i++)
                AuyT[i * TSTRIDE + tid] = un * ky[i];
        }
        __syncthreads();   // AuyT visible; s_conv (written pre-barrier) visible
        if (s_conv) break;
    }

    // ---- epilogue part 1: wd (uses zp from the final u-pass) ----
    //   wd_n = u_n * [ sum_i kx_i*xdis_i*z_i + sum_i kx_i*zy_i ]
    //   z_i = zp (register),  zy_i = sum_j ky_j*ydis_j V[j][i]
    float wdp;
    {
        float ky[16];
#pragma unroll
        for (int i = 0; i < 16; i++) ky[i] = KyT[i * TSTRIDE + tid];
        u64t zyp[8] = {0, 0, 0, 0, 0, 0, 0, 0};
#pragma unroll
        for (int j = 0; j < 16; j++) {
            float dy = py - cood[j];
            float kyy = ky[j] * dy * dy;
            u64t kjy = pack2(kyy, kyy);
            const ulonglong2* Vr = (const ulonglong2*)(Vs + j * 16);
            ulonglong2 v0 = Vr[0], v1 = Vr[1], v2 = Vr[2], v3 = Vr[3];
            fma2(zyp[0], kjy, v0.x); fma2(zyp[1], kjy, v0.y);
            fma2(zyp[2], kjy, v1.x); fma2(zyp[3], kjy, v1.y);
            fma2(zyp[4], kjy, v2.x); fma2(zyp[5], kjy, v2.y);
            fma2(zyp[6], kjy, v3.x); fma2(zyp[7], kjy, v3.y);
        }
        u64t sa = 0, sb = 0;
#pragma unroll
        for (int p = 0; p < 8; p++) {
            float kx0 = KxT[(2 * p) * TSTRIDE + tid];
            float kx1 = KxT[(2 * p + 1) * TSTRIDE + tid];
            float dx0 = px - cood[2 * p];
            float dx1 = px - cood[2 * p + 1];
            fma2(sa, pack2(kx0 * dx0 * dx0, kx1 * dx1 * dx1), zp[p]);
            fma2(sb, pack2(kx0, kx1), zyp[p]);
        }
        wdp = un * hsum2(sa, sb);
    }

    // ---- epilogue part 2: ot, sc, S over the 256 cells ----
    float bt = 0.f, udv = 0.f;
    if (tid < 256) {
        udv = ud[img * 256 + tid];
        bt  = REGP * logf(Vs[tid] + 1e-16f);        // beta
        part[tid]       = bsh[tid] * bt;            // -> ot
        part[256 + tid] = udv;                      // -> sc
        part[512 + tid] = udv * bt;                 // -> S
    }
    __syncthreads();
#pragma unroll
    for (int st = 128; st > 0; st >>= 1) {
        if (tid < st) {
            part[tid]       += part[tid + st];
            part[256 + tid] += part[256 + tid + st];
            part[512 + tid] += part[512 + tid + st];
        }
        __syncthreads();
    }
    const float ot = part[0];
    const float sc = part[256];
    const float S  = part[512];
    const float denom = sc * sc + 1e-8f;
    const float lv = (tid < 256) ? udv * ((sc / denom) * bt - S / denom) : 0.f;

    __syncthreads();   // ot/sc/S consumed; safe to reuse part
    part[tid]        = lv;    // tid>=256 wrote 0
    part[1024 + tid] = wdp;
    __syncthreads();
#pragma unroll
    for (int st = 512; st > 0; st >>= 1) {
        if (tid < st) {
            part[tid]        += part[tid + st];
            part[1024 + tid] += part[1024 + tid + st];
        }
        __syncthreads();
    }

    if (tid == 0) {
        g_partial[img * 3 + 0] = part[0];
        g_partial[img * 3 + 1] = part[1024];
        g_partial[img * 3 + 2] = ot;
        __threadfence();
        unsigned int old = atomicAdd(&g_ctr, 1u);
        s_last = (old == 127u) ? 1 : 0;
    }
    __syncthreads();

    // last-arriving block reduces the 128 per-image partials (fixed tree)
    if (s_last) {
        if (tid == 0) atomicExch(&g_ctr, 0u);
        __threadfence();
        if (tid < 128) {
            part[tid]       = __ldcg(&g_partial[tid * 3 + 0]);
            part[256 + tid] = __ldcg(&g_partial[tid * 3 + 1]);
            part[512 + tid] = __ldcg(&g_partial[tid * 3 + 2]);
        }
        __syncthreads();
#pragma unroll
        for (int st = 64; st > 0; st >>= 1) {
            if (tid < st) {
                part[tid]       += part[tid + st];
                part[256 + tid] += part[256 + tid + st];
                part[512 + tid] += part[512 + tid + st];
            }
            __syncthreads();
        }
        if (tid == 0) {
            out[0] = part[0];
            out[1] = part[256];
            out[2] = part[512];
        }
    }
}

extern "C" void kernel_launch(void* const* d_in, const int* in_sizes, int n_in,
                              void* d_out, int out_size)
{
    const float* nd  = (const float*)d_in[0];
    const float* ud  = (const float*)d_in[1];
    const float* pts = (const float*)d_in[2];

    size_t smem = (size_t)(3 * 16 * TSTRIDE + 3 * 256 + 4096 + 32) * sizeof(float);
    cudaFuncSetAttribute(ot_kernel, cudaFuncAttributeMaxDynamicSharedMemorySize, (int)smem);
    ot_kernel<<<128, 1024, smem>>>(nd, ud, pts, (float*)d_out);
}